// round 13
// baseline (speedup 1.0000x reference)
#include <cuda_runtime.h>
#include <math.h>

#define NN 100000
#define F1 64
#define F2 40
#define NEG_SLOPE 0.2f
#define EPS 1e-16f
#define EMAX 2200000   // Etot = E + NN = 1.7M actual; headroom
#define NB_SCAN ((NN + 255) / 256)   // 391

// ---- scratch (static __device__ arrays; no allocation allowed) ----
__device__ float g_h1[(size_t)NN * F1];
__device__ float g_h2[(size_t)NN * F2];
__device__ float g_as[NN];
__device__ float g_ad[NN];
__device__ float g_as2[NN];
__device__ float g_ad2[NN];
__device__ int   g_deg[NN];
__device__ int   g_rowptr[NN + 1];
__device__ int   g_cursor[NN];
__device__ int   g_esrc[EMAX];
__device__ int   g_part[NB_SCAN];
__device__ int   g_partoff[NB_SCAN];
__device__ int   g_is64;   // 1 if edge_index is int64, 0 if int32

// ---- detect edge_index dtype: int64 values < 2^31 have all-zero high words ----
__global__ void detect_dtype_kernel(const int* __restrict__ ei32, int nwords) {
    __shared__ int any;
    if (threadIdx.x == 0) any = 0;
    __syncthreads();
    int v = 0;
    int limit = 2 * 4096;
    if (limit > nwords) limit = nwords;
    for (int w = 2 * threadIdx.x + 1; w < limit; w += 2 * blockDim.x) v |= ei32[w];
    if (v) atomicOr(&any, 1);
    __syncthreads();
    if (threadIdx.x == 0) g_is64 = (any == 0) ? 1 : 0;
}

__device__ __forceinline__ void edge_endpoints(const void* __restrict__ ei,
                                               int E, int i, int& src, int& dst) {
    if (i >= E) { src = dst = i - E; return; }  // self loop
    if (g_is64) {
        const long long* p = (const long long*)ei;
        src = (int)p[i];
        dst = (int)p[E + i];
    } else {
        const int* p = (const int*)ei;
        src = p[i];
        dst = p[E + i];
    }
}

// ================= CSR build =================
__global__ void init_deg_kernel() {
    int i = blockIdx.x * blockDim.x + threadIdx.x;
    if (i < NN) g_deg[i] = 1;   // self loop
}

// dst-only read
__global__ void count_kernel(const void* __restrict__ ei, int E) {
    int i = blockIdx.x * blockDim.x + threadIdx.x;
    if (i >= E) return;
    int dst;
    if (g_is64) dst = (int)((const long long*)ei)[E + i];
    else        dst = ((const int*)ei)[E + i];
    atomicAdd(&g_deg[dst], 1);
}

// --- scan stage 1: per-block sums of g_deg (256 elems/block) ---
__global__ void block_sum_kernel() {
    __shared__ int red[256];
    int t = threadIdx.x;
    int i = blockIdx.x * 256 + t;
    red[t] = (i < NN) ? g_deg[i] : 0;
    __syncthreads();
    for (int o = 128; o > 0; o >>= 1) {
        if (t < o) red[t] += red[t + o];
        __syncthreads();
    }
    if (t == 0) g_part[blockIdx.x] = red[0];
}

// --- scan stage 2: 1 block scans NB_SCAN partials -> exclusive offsets ---
__global__ void part_scan_kernel() {
    __shared__ int sh[512];
    int t = threadIdx.x;  // 512
    int v = (t < NB_SCAN) ? g_part[t] : 0;
    sh[t] = v;
    __syncthreads();
    for (int o = 1; o < 512; o <<= 1) {
        int u = (t >= o) ? sh[t - o] : 0;
        __syncthreads();
        sh[t] += u;
        __syncthreads();
    }
    if (t < NB_SCAN) g_partoff[t] = sh[t] - v;   // exclusive
    if (t == 511) g_rowptr[NN] = sh[511];        // total
}

// --- scan stage 3: per-block exclusive scan + base -> rowptr/cursor ---
__global__ void rowptr_kernel() {
    __shared__ int sh[256];
    int t = threadIdx.x;
    int i = blockIdx.x * 256 + t;
    int v = (i < NN) ? g_deg[i] : 0;
    sh[t] = v;
    __syncthreads();
    for (int o = 1; o < 256; o <<= 1) {
        int u = (t >= o) ? sh[t - o] : 0;
        __syncthreads();
        sh[t] += u;
        __syncthreads();
    }
    if (i < NN) {
        int r = g_partoff[blockIdx.x] + sh[t] - v;  // exclusive
        g_rowptr[i] = r;
        g_cursor[i] = r;
    }
}

__global__ void scatter_kernel(const void* __restrict__ ei, int E, int Etot) {
    int i = blockIdx.x * blockDim.x + threadIdx.x;
    if (i >= Etot) return;
    int src, dst;
    edge_endpoints(ei, E, i, src, dst);
    int pos = atomicAdd(&g_cursor[dst], 1);
    g_esrc[pos] = src;
}

// ================= layer-1 dense part (tiled) =================
// 256 threads, 32 nodes/block. x: NN x 64 -> h1, as, ad.
__global__ void gemm_alpha_tiled(const float* __restrict__ x,
                                 const float* __restrict__ W,
                                 const float* __restrict__ a_src,
                                 const float* __restrict__ a_dst) {
    constexpr int K = 64, F = 64, NPB = 32, FV = 8;
    __shared__ float xs[NPB][K + 1];
    __shared__ __align__(16) float ws[K * F];

    int tid = threadIdx.x;  // 256
    int nbase = blockIdx.x * NPB;

    {
        const float4* xg = (const float4*)(x + (size_t)nbase * K);
#pragma unroll
        for (int i = 0; i < 2; i++) {
            int idx = tid + i * 256;
            float4 v = __ldg(&xg[idx]);
            int n = idx >> 4;
            int kk = (idx & 15) * 4;
            xs[n][kk] = v.x; xs[n][kk + 1] = v.y;
            xs[n][kk + 2] = v.z; xs[n][kk + 3] = v.w;
        }
    }
    {
        const float4* wg = (const float4*)W;
#pragma unroll
        for (int i = 0; i < 4; i++) ((float4*)ws)[tid + i * 256] = __ldg(&wg[tid + i * 256]);
    }
    __syncthreads();

    int n_local = tid >> 3;
    int fgroup = tid & 7;
    int fbase = fgroup * FV;

    float acc[FV];
#pragma unroll
    for (int i = 0; i < FV; i++) acc[i] = 0.f;

#pragma unroll 16
    for (int k = 0; k < K; k++) {
        float xv = xs[n_local][k];
#pragma unroll
        for (int i = 0; i < FV; i++) acc[i] += xv * ws[k * F + fbase + i];
    }

    int n = nbase + n_local;
    float* hr = g_h1 + (size_t)n * F;
#pragma unroll
    for (int i = 0; i < FV; i++) hr[fbase + i] = acc[i];

    float vs = 0.f, vd = 0.f;
#pragma unroll
    for (int i = 0; i < FV; i++) {
        vs += acc[i] * __ldg(&a_src[fbase + i]);
        vd += acc[i] * __ldg(&a_dst[fbase + i]);
    }
#pragma unroll
    for (int o = 1; o < 8; o <<= 1) {
        vs += __shfl_xor_sync(0xFFFFFFFFu, vs, o);
        vd += __shfl_xor_sync(0xFFFFFFFFu, vd, o);
    }
    if (fgroup == 0) { g_as[n] = vs; g_ad[n] = vd; }
}

// ================= GAT layer 1 + fused gemm2: one warp per dst node ======
// gather/softmax over h1 (F=64), then relu(+b1) and immediately h2 = v@W2,
// as2/ad2 dots. No acc1 round-trip, no separate gemm2 kernel.
__global__ void gat1_fused_kernel(const float* __restrict__ b1,
                                  const float* __restrict__ W2,
                                  const float* __restrict__ a_src2,
                                  const float* __restrict__ a_dst2) {
    constexpr int F = 64, NF4 = 16, EPR = 2;
    __shared__ float sw[8][36];
    __shared__ int   ss[8][36];
    __shared__ float xr[8][64];
    __shared__ float ws2[64 * 40];
    __shared__ float sa2[40], sd2[40];

    int tid = threadIdx.x;  // 256
    // cooperative W2 / a2 load
#pragma unroll
    for (int i = 0; i < 10; i++) {
        int idx = tid + i * 256;
        if (idx < 64 * 40) ws2[idx] = __ldg(&W2[idx]);
    }
    if (tid < 40) { sa2[tid] = __ldg(&a_src2[tid]); sd2[tid] = __ldg(&a_dst2[tid]); }
    __syncthreads();

    int wslot = tid >> 5;
    int lane = tid & 31;
    if (lane < 4) { sw[wslot][32 + lane] = 0.f; ss[wslot][32 + lane] = 0; }

    int n = blockIdx.x * 8 + wslot;   // grid = NN/8 exactly
    int sub = lane >> 4;              // lane / NF4
    int c   = lane & 15;              // lane % NF4

    int row = g_rowptr[n];
    int end = g_rowptr[n + 1];
    float adn = g_ad[n];

    float M = -INFINITY, s_sum = 0.f;
    float4 acc = make_float4(0.f, 0.f, 0.f, 0.f);

    for (int base = row; base < end; base += 32) {
        int e = base + lane;
        float sc = -INFINITY;
        int src = 0;
        if (e < end) {
            src = __ldg(&g_esrc[e]);
            sc = __ldg(&g_as[src]) + adn;
            sc = sc > 0.f ? sc : NEG_SLOPE * sc;
        }
        float cm = sc;
#pragma unroll
        for (int o = 16; o > 0; o >>= 1) cm = fmaxf(cm, __shfl_xor_sync(0xFFFFFFFFu, cm, o));
        float newM = fmaxf(M, cm);
        float scale = __expf(M - newM);
        s_sum *= scale;
        acc.x *= scale; acc.y *= scale; acc.z *= scale; acc.w *= scale;

        float w = (e < end) ? __expf(sc - newM) : 0.f;
        s_sum += w;
        sw[wslot][lane] = w;
        ss[wslot][lane] = src;
        __syncwarp();

#pragma unroll
        for (int j2 = 0; j2 < 32; j2 += EPR) {
            int j = j2 + sub;
            float wj = sw[wslot][j];
            const float4* hs = (const float4*)(g_h1 + (size_t)ss[wslot][j] * F);
            float4 v = __ldg(&hs[c]);
            acc.x += wj * v.x; acc.y += wj * v.y;
            acc.z += wj * v.z; acc.w += wj * v.w;
        }
        __syncwarp();
        M = newM;
    }
#pragma unroll
    for (int o = 16; o > 0; o >>= 1) s_sum += __shfl_xor_sync(0xFFFFFFFFu, s_sum, o);
    float inv = 1.f / (s_sum + EPS);

    acc.x += __shfl_xor_sync(0xFFFFFFFFu, acc.x, 16);
    acc.y += __shfl_xor_sync(0xFFFFFFFFu, acc.y, 16);
    acc.z += __shfl_xor_sync(0xFFFFFFFFu, acc.z, 16);
    acc.w += __shfl_xor_sync(0xFFFFFFFFu, acc.w, 16);

    // relu(acc/s + b1) -> stage to smem (layer-2 input vector)
    if (lane < NF4) {
        float4 bb = ((const float4*)b1)[c];
        float4 v;
        v.x = fmaxf(acc.x * inv + bb.x, 0.f);
        v.y = fmaxf(acc.y * inv + bb.y, 0.f);
        v.z = fmaxf(acc.z * inv + bb.z, 0.f);
        v.w = fmaxf(acc.w * inv + bb.w, 0.f);
        ((float4*)xr[wslot])[c] = v;
    }
    __syncwarp();

    // fused gemm2: h2[n] = v @ W2 (64->40); lane computes f=lane and f=lane+32
    float s0 = 0.f, s1 = 0.f;
#pragma unroll 16
    for (int k = 0; k < 64; k++) {
        float xv = xr[wslot][k];
        s0 += xv * ws2[k * 40 + lane];
        if (lane < 8) s1 += xv * ws2[k * 40 + lane + 32];
    }
    float* h2r = g_h2 + (size_t)n * 40;
    h2r[lane] = s0;
    if (lane < 8) h2r[lane + 32] = s1;

    float vs = s0 * sa2[lane] + (lane < 8 ? s1 * sa2[lane + 32] : 0.f);
    float vd = s0 * sd2[lane] + (lane < 8 ? s1 * sd2[lane + 32] : 0.f);
#pragma unroll
    for (int o = 16; o > 0; o >>= 1) {
        vs += __shfl_xor_sync(0xFFFFFFFFu, vs, o);
        vd += __shfl_xor_sync(0xFFFFFFFFu, vd, o);
    }
    if (lane == 0) { g_as2[n] = vs; g_ad2[n] = vd; }
}

// ================= GAT layer 2: one warp per dst node + log_softmax ======
__global__ void gat2_kernel(const float* __restrict__ b,
                            float* __restrict__ out) {
    constexpr int F = 40, NF4 = 10, EPR = 3;
    __shared__ float sw[8][36];
    __shared__ int   ss[8][36];

    int wslot = threadIdx.x >> 5;
    int lane = threadIdx.x & 31;
    if (lane < 4) { sw[wslot][32 + lane] = 0.f; ss[wslot][32 + lane] = 0; }
    __syncwarp();

    int n = blockIdx.x * 8 + wslot;   // grid = NN/8 exactly
    int sub = lane / NF4;
    int c   = lane % NF4;
    bool active = sub < EPR;

    int row = g_rowptr[n];
    int end = g_rowptr[n + 1];
    float adn = g_ad2[n];

    float M = -INFINITY, s_sum = 0.f;
    float4 acc = make_float4(0.f, 0.f, 0.f, 0.f);

    for (int base = row; base < end; base += 32) {
        int e = base + lane;
        float sc = -INFINITY;
        int src = 0;
        if (e < end) {
            src = __ldg(&g_esrc[e]);
            sc = __ldg(&g_as2[src]) + adn;
            sc = sc > 0.f ? sc : NEG_SLOPE * sc;
        }
        float cm = sc;
#pragma unroll
        for (int o = 16; o > 0; o >>= 1) cm = fmaxf(cm, __shfl_xor_sync(0xFFFFFFFFu, cm, o));
        float newM = fmaxf(M, cm);
        float scale = __expf(M - newM);
        s_sum *= scale;
        acc.x *= scale; acc.y *= scale; acc.z *= scale; acc.w *= scale;

        float w = (e < end) ? __expf(sc - newM) : 0.f;
        s_sum += w;
        sw[wslot][lane] = w;
        ss[wslot][lane] = src;
        __syncwarp();

#pragma unroll
        for (int j2 = 0; j2 < 32; j2 += EPR) {
            int j = j2 + sub;
            float wj = active ? sw[wslot][j] : 0.f;
            const float4* hs = (const float4*)(g_h2 + (size_t)ss[wslot][j] * F);
            float4 v = __ldg(&hs[c]);
            acc.x += wj * v.x; acc.y += wj * v.y;
            acc.z += wj * v.z; acc.w += wj * v.w;
        }
        __syncwarp();
        M = newM;
    }
#pragma unroll
    for (int o = 16; o > 0; o >>= 1) s_sum += __shfl_xor_sync(0xFFFFFFFFu, s_sum, o);
    float inv = 1.f / (s_sum + EPS);

    // combine 3 subs -> lanes 0..9
    int l1 = lane + NF4, l2 = lane + 2 * NF4;
    float x1 = __shfl_sync(0xFFFFFFFFu, acc.x, l1 & 31), x2 = __shfl_sync(0xFFFFFFFFu, acc.x, l2 & 31);
    float y1 = __shfl_sync(0xFFFFFFFFu, acc.y, l1 & 31), y2 = __shfl_sync(0xFFFFFFFFu, acc.y, l2 & 31);
    float z1 = __shfl_sync(0xFFFFFFFFu, acc.z, l1 & 31), z2 = __shfl_sync(0xFFFFFFFFu, acc.z, l2 & 31);
    float w1 = __shfl_sync(0xFFFFFFFFu, acc.w, l1 & 31), w2 = __shfl_sync(0xFFFFFFFFu, acc.w, l2 & 31);
    acc.x += x1 + x2; acc.y += y1 + y2; acc.z += z1 + z2; acc.w += w1 + w2;

    float4 v = make_float4(-INFINITY, -INFINITY, -INFINITY, -INFINITY);
    if (lane < NF4) {
        float4 bb = ((const float4*)b)[c];
        v.x = acc.x * inv + bb.x;
        v.y = acc.y * inv + bb.y;
        v.z = acc.z * inv + bb.z;
        v.w = acc.w * inv + bb.w;
    }
    float mx = fmaxf(fmaxf(v.x, v.y), fmaxf(v.z, v.w));
#pragma unroll
    for (int o = 16; o > 0; o >>= 1) mx = fmaxf(mx, __shfl_xor_sync(0xFFFFFFFFu, mx, o));
    float es = 0.f;
    if (lane < NF4)
        es = __expf(v.x - mx) + __expf(v.y - mx) + __expf(v.z - mx) + __expf(v.w - mx);
#pragma unroll
    for (int o = 16; o > 0; o >>= 1) es += __shfl_xor_sync(0xFFFFFFFFu, es, o);
    float lse = mx + logf(es);
    if (lane < NF4) {
        float4 r;
        r.x = v.x - lse; r.y = v.y - lse; r.z = v.z - lse; r.w = v.w - lse;
        ((float4*)(out + (size_t)n * F))[c] = r;
    }
}

extern "C" void kernel_launch(void* const* d_in, const int* in_sizes, int n_in,
                              void* d_out, int out_size) {
    const float* x      = (const float*)d_in[0];
    const void*  ei     = d_in[1];
    const float* W1     = (const float*)d_in[2];
    const float* a_src1 = (const float*)d_in[3];
    const float* a_dst1 = (const float*)d_in[4];
    const float* b1     = (const float*)d_in[5];
    const float* W2     = (const float*)d_in[6];
    const float* a_src2 = (const float*)d_in[7];
    const float* a_dst2 = (const float*)d_in[8];
    const float* b2     = (const float*)d_in[9];
    float* out = (float*)d_out;

    int E = in_sizes[1] / 2;
    int Etot = E + NN;

    const int TB = 256;
    int eb  = (E + TB - 1) / TB;
    int etb = (Etot + TB - 1) / TB;
    int nb  = (NN + TB - 1) / TB;
    int gat_blocks = NN / 8;     // 12500 exact
    int gemm_blocks = NN / 32;   // 3125 exact

    // launches 1-3: dtype + degree count
    detect_dtype_kernel<<<1, 256>>>((const int*)ei, in_sizes[1]);
    init_deg_kernel<<<nb, TB>>>();
    count_kernel<<<eb, TB>>>(ei, E);
    // launch 4 (ncu capture slot): layer-1 gemm — independent of CSR
    gemm_alpha_tiled<<<gemm_blocks, 256>>>(x, W1, a_src1, a_dst1);
    // launches 5-8: scan + scatter
    block_sum_kernel<<<NB_SCAN, 256>>>();
    part_scan_kernel<<<1, 512>>>();
    rowptr_kernel<<<NB_SCAN, 256>>>();
    scatter_kernel<<<etb, TB>>>(ei, E, Etot);
    // launch 9: gat layer 1 + fused gemm2
    gat1_fused_kernel<<<gat_blocks, 256>>>(b1, W2, a_src2, a_dst2);
    // launch 10: gat layer 2 + log_softmax
    gat2_kernel<<<gat_blocks, 256>>>(b2, out);
}

// round 15
// speedup vs baseline: 1.3992x; 1.3992x over previous
#include <cuda_runtime.h>
#include <math.h>

#define NN 100000
#define F1 64
#define F2 40
#define NEG_SLOPE 0.2f
#define EPS 1e-16f
#define EMAX 2200000
#define NB_SCAN ((NN + 255) / 256)   // 391
#define NPB 128                      // nodes per gemm block
#define GEMM_BLOCKS ((NN + NPB - 1) / NPB)   // 782

// ---- scratch ----
__device__ float g_h1[(size_t)NN * F1];
__device__ float g_acc1[(size_t)NN * F1];
__device__ float g_h2[(size_t)NN * F2];
__device__ float g_as[NN];
__device__ float g_ad[NN];
__device__ int   g_deg[NN];
__device__ int   g_rowptr[NN + 1];
__device__ int   g_cursor[NN];
__device__ int   g_esrc[EMAX];
__device__ int   g_part[NB_SCAN];
__device__ int   g_partoff[NB_SCAN];
__device__ int   g_is64;

// ---- dtype probe ----
__global__ void detect_dtype_kernel(const int* __restrict__ ei32, int nwords) {
    __shared__ int any;
    if (threadIdx.x == 0) any = 0;
    __syncthreads();
    int v = 0;
    int limit = 2 * 4096;
    if (limit > nwords) limit = nwords;
    for (int w = 2 * threadIdx.x + 1; w < limit; w += 2 * blockDim.x) v |= ei32[w];
    if (v) atomicOr(&any, 1);
    __syncthreads();
    if (threadIdx.x == 0) g_is64 = (any == 0) ? 1 : 0;
}

__device__ __forceinline__ void edge_endpoints(const void* __restrict__ ei,
                                               int E, int i, int& src, int& dst) {
    if (i >= E) { src = dst = i - E; return; }
    if (g_is64) {
        const long long* p = (const long long*)ei;
        src = (int)p[i];
        dst = (int)p[E + i];
    } else {
        const int* p = (const int*)ei;
        src = p[i];
        dst = p[E + i];
    }
}

// ================= CSR build =================
__global__ void init_deg_kernel() {
    int i = blockIdx.x * blockDim.x + threadIdx.x;
    if (i < NN) g_deg[i] = 1;
}

__global__ void count_kernel(const void* __restrict__ ei, int E) {
    int i = blockIdx.x * blockDim.x + threadIdx.x;
    if (i >= E) return;
    int dst;
    if (g_is64) dst = (int)((const long long*)ei)[E + i];
    else        dst = ((const int*)ei)[E + i];
    atomicAdd(&g_deg[dst], 1);
}

__global__ void block_sum_kernel() {
    __shared__ int red[256];
    int t = threadIdx.x;
    int i = blockIdx.x * 256 + t;
    red[t] = (i < NN) ? g_deg[i] : 0;
    __syncthreads();
    for (int o = 128; o > 0; o >>= 1) {
        if (t < o) red[t] += red[t + o];
        __syncthreads();
    }
    if (t == 0) g_part[blockIdx.x] = red[0];
}

__global__ void part_scan_kernel() {
    __shared__ int sh[512];
    int t = threadIdx.x;
    int v = (t < NB_SCAN) ? g_part[t] : 0;
    sh[t] = v;
    __syncthreads();
    for (int o = 1; o < 512; o <<= 1) {
        int u = (t >= o) ? sh[t - o] : 0;
        __syncthreads();
        sh[t] += u;
        __syncthreads();
    }
    if (t < NB_SCAN) g_partoff[t] = sh[t] - v;
    if (t == 511) g_rowptr[NN] = sh[511];
}

__global__ void rowptr_kernel() {
    __shared__ int sh[256];
    int t = threadIdx.x;
    int i = blockIdx.x * 256 + t;
    int v = (i < NN) ? g_deg[i] : 0;
    sh[t] = v;
    __syncthreads();
    for (int o = 1; o < 256; o <<= 1) {
        int u = (t >= o) ? sh[t - o] : 0;
        __syncthreads();
        sh[t] += u;
        __syncthreads();
    }
    if (i < NN) {
        int r = g_partoff[blockIdx.x] + sh[t] - v;
        g_rowptr[i] = r;
        g_cursor[i] = r;
    }
}

__global__ void scatter_kernel(const void* __restrict__ ei, int E, int Etot) {
    int i = blockIdx.x * blockDim.x + threadIdx.x;
    if (i >= Etot) return;
    int src, dst;
    edge_endpoints(ei, E, i, src, dst);
    int pos = atomicAdd(&g_cursor[dst], 1);
    g_esrc[pos] = src;
}

// ================= register-blocked GEMM: h = xin @ W =================
// blockDim = (F/4)*32; each thread: 4 nodes x 4 outputs (16 FMA per k from
// 1 LDS.128 of W + 4 broadcast x loads). 128 nodes/block.
template <int F, int LAYER>
__global__ void gemm_reg(const float* __restrict__ x,
                         const float* __restrict__ W) {
    constexpr int K = 64;
    constexpr int FG = F / 4;
    constexpr int NTHR = FG * 32;
    const float* xin = (LAYER == 1) ? x : g_acc1;
    float* h = (LAYER == 1) ? g_h1 : g_h2;

    __shared__ float xs[NPB][K + 1];
    __shared__ __align__(16) float ws[K * F];

    int tid = threadIdx.x;
    int nbase = blockIdx.x * NPB;
    int nrem = NN - nbase;
    if (nrem > NPB) nrem = NPB;

    // x tile: nrem*K floats as float4
    {
        const float4* xg = (const float4*)(xin + (size_t)nbase * K);
        int tot4 = nrem * (K / 4);
        for (int idx = tid; idx < tot4; idx += NTHR) {
            float4 v = __ldg(&xg[idx]);
            int n = idx >> 4;
            int kk = (idx & 15) * 4;
            xs[n][kk] = v.x; xs[n][kk + 1] = v.y;
            xs[n][kk + 2] = v.z; xs[n][kk + 3] = v.w;
        }
    }
    // W: K*F floats
    for (int idx = tid; idx < K * F / 4; idx += NTHR)
        ((float4*)ws)[idx] = __ldg(&((const float4*)W)[idx]);
    __syncthreads();

    int fgroup = tid % FG;
    int ngroup = tid / FG;      // 0..31
    int nloc = ngroup * 4;

    float acc[4][4];
#pragma unroll
    for (int j = 0; j < 4; j++)
#pragma unroll
        for (int i = 0; i < 4; i++) acc[j][i] = 0.f;

#pragma unroll 8
    for (int k = 0; k < K; k++) {
        float4 w = ((const float4*)(ws + k * F))[fgroup];
#pragma unroll
        for (int j = 0; j < 4; j++) {
            float xv = xs[nloc + j][k];
            acc[j][0] += xv * w.x; acc[j][1] += xv * w.y;
            acc[j][2] += xv * w.z; acc[j][3] += xv * w.w;
        }
    }

#pragma unroll
    for (int j = 0; j < 4; j++) {
        int n = nbase + nloc + j;
        if (n < NN) {
            float4 v = make_float4(acc[j][0], acc[j][1], acc[j][2], acc[j][3]);
            ((float4*)(h + (size_t)n * F))[fgroup] = v;
        }
    }
}

// ================= alpha: as = h.a_src, ad = h.a_dst (warp per node) ======
template <int F, int LAYER>
__global__ void alpha_kernel(const float* __restrict__ a_src,
                             const float* __restrict__ a_dst) {
    const float* h = (LAYER == 1) ? g_h1 : g_h2;
    int gw = (blockIdx.x * blockDim.x + threadIdx.x) >> 5;
    int lane = threadIdx.x & 31;
    if (gw >= NN) return;
    float vs = 0.f, vd = 0.f;
    if (lane * 2 < F) {
        float2 v = __ldg(&((const float2*)(h + (size_t)gw * F))[lane]);
        float2 as = __ldg(&((const float2*)a_src)[lane]);
        float2 ad = __ldg(&((const float2*)a_dst)[lane]);
        vs = v.x * as.x + v.y * as.y;
        vd = v.x * ad.x + v.y * ad.y;
    }
#pragma unroll
    for (int o = 16; o > 0; o >>= 1) {
        vs += __shfl_xor_sync(0xFFFFFFFFu, vs, o);
        vd += __shfl_xor_sync(0xFFFFFFFFu, vd, o);
    }
    if (lane == 0) { g_as[gw] = vs; g_ad[gw] = vd; }
}

// ================= GAT aggregation: one warp per dst node =================
template <int F, int LAYER>
__global__ void gat_node_kernel(const float* __restrict__ b,
                                float* __restrict__ out) {
    const float* __restrict__ h = (LAYER == 1) ? g_h1 : g_h2;
    constexpr int NF4 = F / 4;
    constexpr int EPR = 32 / NF4;

    __shared__ float sw[8][36];
    __shared__ int   ss[8][36];

    int wslot = threadIdx.x >> 5;
    int lane = threadIdx.x & 31;
    if (lane < 4) { sw[wslot][32 + lane] = 0.f; ss[wslot][32 + lane] = 0; }
    __syncwarp();

    int n = blockIdx.x * 8 + wslot;
    if (n >= NN) return;

    int sub = lane / NF4;
    int c   = lane % NF4;
    bool active = sub < EPR;

    int row = g_rowptr[n];
    int end = g_rowptr[n + 1];
    float adn = g_ad[n];

    float M = -INFINITY, s_sum = 0.f;
    float4 acc = make_float4(0.f, 0.f, 0.f, 0.f);

    for (int base = row; base < end; base += 32) {
        int e = base + lane;
        float sc = -INFINITY;
        int src = 0;
        if (e < end) {
            src = __ldg(&g_esrc[e]);
            sc = __ldg(&g_as[src]) + adn;
            sc = sc > 0.f ? sc : NEG_SLOPE * sc;
        }
        float cm = sc;
#pragma unroll
        for (int o = 16; o > 0; o >>= 1) cm = fmaxf(cm, __shfl_xor_sync(0xFFFFFFFFu, cm, o));
        float newM = fmaxf(M, cm);
        float scale = __expf(M - newM);
        s_sum *= scale;
        acc.x *= scale; acc.y *= scale; acc.z *= scale; acc.w *= scale;

        float w = (e < end) ? __expf(sc - newM) : 0.f;
        s_sum += w;
        sw[wslot][lane] = w;
        ss[wslot][lane] = src;
        __syncwarp();

#pragma unroll
        for (int j2 = 0; j2 < 32; j2 += EPR) {
            int j = j2 + sub;
            float wj = active ? sw[wslot][j] : 0.f;
            const float4* hs = (const float4*)(h + (size_t)ss[wslot][j] * F);
            float4 v = __ldg(&hs[c]);
            acc.x += wj * v.x; acc.y += wj * v.y;
            acc.z += wj * v.z; acc.w += wj * v.w;
        }
        __syncwarp();
        M = newM;
    }
#pragma unroll
    for (int o = 16; o > 0; o >>= 1) s_sum += __shfl_xor_sync(0xFFFFFFFFu, s_sum, o);
    float inv = 1.f / (s_sum + EPS);

    if (EPR == 2) {
        acc.x += __shfl_xor_sync(0xFFFFFFFFu, acc.x, 16);
        acc.y += __shfl_xor_sync(0xFFFFFFFFu, acc.y, 16);
        acc.z += __shfl_xor_sync(0xFFFFFFFFu, acc.z, 16);
        acc.w += __shfl_xor_sync(0xFFFFFFFFu, acc.w, 16);
    } else {
        int l1 = lane + NF4, l2 = lane + 2 * NF4;
        float x1 = __shfl_sync(0xFFFFFFFFu, acc.x, l1 & 31), x2 = __shfl_sync(0xFFFFFFFFu, acc.x, l2 & 31);
        float y1 = __shfl_sync(0xFFFFFFFFu, acc.y, l1 & 31), y2 = __shfl_sync(0xFFFFFFFFu, acc.y, l2 & 31);
        float z1 = __shfl_sync(0xFFFFFFFFu, acc.z, l1 & 31), z2 = __shfl_sync(0xFFFFFFFFu, acc.z, l2 & 31);
        float w1 = __shfl_sync(0xFFFFFFFFu, acc.w, l1 & 31), w2 = __shfl_sync(0xFFFFFFFFu, acc.w, l2 & 31);
        acc.x += x1 + x2; acc.y += y1 + y2; acc.z += z1 + z2; acc.w += w1 + w2;
    }

    const float4* b4 = (const float4*)b;
    if (LAYER == 1) {
        if (lane < NF4) {
            float4 bb = b4[c];
            float4 v;
            v.x = fmaxf(acc.x * inv + bb.x, 0.f);
            v.y = fmaxf(acc.y * inv + bb.y, 0.f);
            v.z = fmaxf(acc.z * inv + bb.z, 0.f);
            v.w = fmaxf(acc.w * inv + bb.w, 0.f);
            ((float4*)(g_acc1 + (size_t)n * F))[c] = v;
        }
    } else {
        float4 v = make_float4(-INFINITY, -INFINITY, -INFINITY, -INFINITY);
        if (lane < NF4) {
            float4 bb = b4[c];
            v.x = acc.x * inv + bb.x;
            v.y = acc.y * inv + bb.y;
            v.z = acc.z * inv + bb.z;
            v.w = acc.w * inv + bb.w;
        }
        float mx = fmaxf(fmaxf(v.x, v.y), fmaxf(v.z, v.w));
#pragma unroll
        for (int o = 16; o > 0; o >>= 1) mx = fmaxf(mx, __shfl_xor_sync(0xFFFFFFFFu, mx, o));
        float es = 0.f;
        if (lane < NF4)
            es = __expf(v.x - mx) + __expf(v.y - mx) + __expf(v.z - mx) + __expf(v.w - mx);
#pragma unroll
        for (int o = 16; o > 0; o >>= 1) es += __shfl_xor_sync(0xFFFFFFFFu, es, o);
        float lse = mx + logf(es);
        if (lane < NF4) {
            float4 r;
            r.x = v.x - lse; r.y = v.y - lse; r.z = v.z - lse; r.w = v.w - lse;
            ((float4*)(out + (size_t)n * F))[c] = r;
        }
    }
}

extern "C" void kernel_launch(void* const* d_in, const int* in_sizes, int n_in,
                              void* d_out, int out_size) {
    const float* x      = (const float*)d_in[0];
    const void*  ei     = d_in[1];
    const float* W1     = (const float*)d_in[2];
    const float* a_src1 = (const float*)d_in[3];
    const float* a_dst1 = (const float*)d_in[4];
    const float* b1     = (const float*)d_in[5];
    const float* W2     = (const float*)d_in[6];
    const float* a_src2 = (const float*)d_in[7];
    const float* a_dst2 = (const float*)d_in[8];
    const float* b2     = (const float*)d_in[9];
    float* out = (float*)d_out;

    int E = in_sizes[1] / 2;
    int Etot = E + NN;

    const int TB = 256;
    int eb  = (E + TB - 1) / TB;
    int etb = (Etot + TB - 1) / TB;
    int nb  = (NN + TB - 1) / TB;
    int gat_blocks = (NN + 7) / 8;
    int warp_node_blocks = (NN * 32 + TB - 1) / TB;

    // launches 1-3
    detect_dtype_kernel<<<1, 256>>>((const int*)ei, in_sizes[1]);
    init_deg_kernel<<<nb, TB>>>();
    count_kernel<<<eb, TB>>>(ei, E);
    // launch 4 (ncu capture slot): the rewritten layer-1 GEMM
    gemm_reg<F1, 1><<<GEMM_BLOCKS, (F1 / 4) * 32>>>(x, W1);
    // CSR scan + scatter
    block_sum_kernel<<<NB_SCAN, 256>>>();
    part_scan_kernel<<<1, 512>>>();
    rowptr_kernel<<<NB_SCAN, 256>>>();
    scatter_kernel<<<etb, TB>>>(ei, E, Etot);
    // layer 1
    alpha_kernel<F1, 1><<<warp_node_blocks, TB>>>(a_src1, a_dst1);
    gat_node_kernel<F1, 1><<<gat_blocks, 256>>>(b1, nullptr);
    // layer 2
    gemm_reg<F2, 2><<<GEMM_BLOCKS, (F2 / 4) * 32>>>(nullptr, W2);
    alpha_kernel<F2, 2><<<warp_node_blocks, TB>>>(a_src2, a_dst2);
    gat_node_kernel<F2, 2><<<gat_blocks, 256>>>(b2, out);
}